// round 12
// baseline (speedup 1.0000x reference)
#include <cuda_runtime.h>
#include <stdint.h>

// InfoNCE loss with exact JAX partitionable threefry2x32-20 sampling.
// bits[p] = x0 ^ x1 of threefry2x32(key=(0,42), counter=(0, p)), p = row*E+col.
//
// Single persistent-wave kernel: 1024 CTAs x 4 rows each (one full wave,
// no wave quantization / CTA spread). Branch-free predicated hit-push with
// address-carrying shared counter (6 instrs/elem). Last-CTA reduction.

#define TEMP    0.07f
#define MAXB    384        // unified buffer: E[n]~161 (128 cand + 33 pos), >15 sigma
#define MAXP    128        // positives per row (expected ~33)
#define BITSCUT (1u << 25) // bits < 2^25  <=>  u < 1/128
#define NROWS   4096

static __device__ double g_rowLoss[NROWS];
static __device__ int    g_rowPairs[NROWS];
static __device__ unsigned int g_done = 0;

__device__ __forceinline__ uint32_t rotl32(uint32_t v, int r) {
    return __funnelshift_l(v, v, r);
}

// Threefry-2x32, 20 rounds, key=(0,42), counter=(0,p).
// xin must be p + 42 (= p + ks1, caller folds). Returns x0out ^ x1out.
__device__ __forceinline__ uint32_t threefry_bits(uint32_t xin) {
    const uint32_t ks1 = 42u;
    const uint32_t ks2 = 0x1BD11BDAu ^ 42u;
    uint32_t x1 = xin;
    uint32_t x0 = x1;                       // round 1 add from x0=0
    x1 = rotl32(x1, 13) ^ x0;
    x0 += x1;        x1 = rotl32(x1, 15) ^ x0;
    x0 += x1;        x1 = rotl32(x1, 26) ^ x0;
    x0 += x1;        x1 = rotl32(x1,  6) ^ x0;
    x1 += ks2 + 1u;                         // x1 injection, then x0 inj folds:
    x0 += x1 + ks1;  x1 = rotl32(x1, 17) ^ x0;
    x0 += x1;        x1 = rotl32(x1, 29) ^ x0;
    x0 += x1;        x1 = rotl32(x1, 16) ^ x0;
    x0 += x1;        x1 = rotl32(x1, 24) ^ x0;
    x1 += 2u;
    x0 += x1 + ks2;  x1 = rotl32(x1, 13) ^ x0;
    x0 += x1;        x1 = rotl32(x1, 15) ^ x0;
    x0 += x1;        x1 = rotl32(x1, 26) ^ x0;
    x0 += x1;        x1 = rotl32(x1,  6) ^ x0;
    x1 += ks1 + 3u;                         // x0 += ks0(=0): nothing
    x0 += x1;        x1 = rotl32(x1, 17) ^ x0;
    x0 += x1;        x1 = rotl32(x1, 29) ^ x0;
    x0 += x1;        x1 = rotl32(x1, 16) ^ x0;
    x0 += x1;        x1 = rotl32(x1, 24) ^ x0;
    x1 += ks2 + 4u;
    x0 += x1 + ks1;  x1 = rotl32(x1, 13) ^ x0;
    x0 += x1;        x1 = rotl32(x1, 15) ^ x0;
    x0 += x1;        x1 = rotl32(x1, 26) ^ x0;
    x0 += x1;        x1 = rotl32(x1,  6) ^ x0;
    return (x0 + ks2) ^ (x1 + 5u);
}

// Branch-free hit push (6 instrs): the shared counter holds the NEXT WRITE
// ADDRESS (byte address in smem); atom.add 8 returns the slot address.
__device__ __forceinline__ void push_hit(int a, uint32_t bits, uint32_t col,
                                         uint32_t ctr_addr, uint32_t buf_end) {
    asm volatile(
        "{\n\t"
        ".reg .pred p1, p, pb;\n\t"
        ".reg .u32 v, adr;\n\t"
        "setp.gt.s32 p1, %0, 0;\n\t"
        "setp.lt.or.u32 p, %1, %2, p1;\n\t"
        "selp.b32 v, 0xFFFFFFFF, %1, p1;\n\t"
        "@p atom.shared.add.u32 adr, [%3], 8;\n\t"
        "setp.lt.and.u32 pb, adr, %4, p;\n\t"
        "@pb st.shared.v2.u32 [adr], {%5, v};\n\t"
        "}"
        :: "r"(a), "r"(bits), "r"(BITSCUT), "r"(ctr_addr),
           "r"(buf_end), "r"(col)
        : "memory");
}

__global__ __launch_bounds__(256, 7)
void infonce_row(const float* __restrict__ item,
                 const float* __restrict__ ent,
                 const int*   __restrict__ adj,
                 float* __restrict__ out,
                 int E, int I)
{
    __shared__ float4             s_it4[16];      // item row * 1/(||it||*T)
    __shared__ unsigned long long s_buf[MAXB];    // {col(lo32), key(hi32)}
    __shared__ unsigned short     s_pos[MAXP];    // positives, sorted by col
    __shared__ unsigned short     s_sel[MAXP];    // selected negs, by rank
    __shared__ float              s_simN[MAXP];
    __shared__ float              s_simP[MAXP];
    __shared__ unsigned int       s_n;            // write-address counter
    __shared__ int                s_npc, s_last;
    __shared__ float              s_mS[2];
    __shared__ double             s_red[256];
    __shared__ long long          s_redp[256];

    float* s_it = (float*)s_it4;

    const int tid    = threadIdx.x;
    const int lane   = tid & 31;
    const int warpId = tid >> 5;

    const uint32_t ctr_addr = (uint32_t)__cvta_generic_to_shared(&s_n);
    const uint32_t buf_addr = (uint32_t)__cvta_generic_to_shared(&s_buf[0]);
    const uint32_t buf_end  = buf_addr + MAXB * 8u;

    // -------- persistent row loop: 4 rows per CTA, one full wave ----------
    for (int row = blockIdx.x; row < I; row += gridDim.x) {

        if (tid == 0) { s_n = buf_addr; s_npc = 0; }
        if (tid < 64) s_it[tid] = item[(size_t)row * 64 + tid];
        __syncthreads();
        if (tid < 32) {
            float a = s_it[lane], b = s_it[lane + 32];
            float ss = a * a + b * b;
            #pragma unroll
            for (int o = 16; o; o >>= 1) ss += __shfl_down_sync(0xffffffffu, ss, o);
            ss = __shfl_sync(0xffffffffu, ss, 0);
            float sc = 1.0f / (sqrtf(ss) * TEMP);
            s_it[lane]      = a * sc;
            s_it[lane + 32] = b * sc;
        }
        __syncthreads();

        const uint32_t base = (uint32_t)row * (uint32_t)E;
        const int* adjR = adj + (size_t)row * E;

        // ---- streaming pass: threefry + adj scan, branch-free, prefetched --
        int c0 = tid * 8;
        int4 pa = *(const int4*)(adjR + c0);
        int4 pb = *(const int4*)(adjR + c0 + 4);
        #pragma unroll 1
        while (c0 < E) {
            const int4 ca = pa, cb = pb;
            const int cn = c0 + 2048;
            const int cs = (cn < E) ? cn : c0;        // safe prefetch address
            pa = *(const int4*)(adjR + cs);
            pb = *(const int4*)(adjR + cs + 4);

            const uint32_t pb42 = base + (uint32_t)c0 + 42u;  // p + ks1 base
            #pragma unroll
            for (int j = 0; j < 8; ++j) {
                uint32_t bits = threefry_bits(pb42 + (uint32_t)j);
                int a = (j==0)?ca.x:(j==1)?ca.y:(j==2)?ca.z:(j==3)?ca.w:
                        (j==4)?cb.x:(j==5)?cb.y:(j==6)?cb.z:cb.w;
                push_hit(a, bits, (uint32_t)c0 + (uint32_t)j, ctr_addr, buf_end);
            }
            c0 = cn;
        }
        __syncthreads();

        // ---- selection: one rank pass over unified buffer ------------------
        const int n = min((int)((s_n - buf_addr) >> 3), MAXB);

        // count positives + normalize keys:
        //   candidates: (bits>>9)<<16 | col   positives: 2^32 | col (above all)
        for (int i = tid; i < n; i += 256) {
            unsigned long long e = s_buf[i];
            uint32_t hi  = (uint32_t)(e >> 32);
            uint32_t col = (uint32_t)e & 0xFFFFu;
            bool isP = (hi == 0xFFFFFFFFu);
            if (isP) atomicAdd(&s_npc, 1);
            s_buf[i] = isP ? ((1ULL << 32) | col)
                           : ((((unsigned long long)(hi >> 9)) << 16) | col);
        }
        __syncthreads();

        const int npT   = s_npc;
        const int np    = min(npT, MAXP);
        const int k     = np;             // k = min(num_pos, num_neg) = num_pos
        const int ncand = n - npT;
        const int ksel  = min(k, min(ncand, MAXP));

        for (int i = tid; i < n; i += 256) {
            unsigned long long v = s_buf[i];
            int rank = 0;
            for (int j = 0; j < n; ++j) rank += (s_buf[j] < v);
            uint32_t col = (uint32_t)v & 0xFFFFu;
            if (v >= (1ULL << 32)) {
                int pr = rank - ncand;             // positives rank above cands
                if (pr >= 0 && pr < MAXP) s_pos[pr] = (unsigned short)col;
            } else if (rank < ksel) {
                s_sel[rank] = (unsigned short)col;
            }
        }
        __syncthreads();

        // ---- cosine sims: 4 threads per entity row, 64 concurrent ----------
        {
            const int total = ksel + np;   // negatives first, then positives
            const int q = tid & 3;
            #pragma unroll 1
            for (int s0 = 0; s0 < total; s0 += 64) {
                const int s = s0 + (tid >> 2);
                const bool act = (s < total);
                float dot = 0.0f, ssq = 0.0f;
                if (act) {
                    int c = (s < ksel) ? s_sel[s] : s_pos[s - ksel];
                    const float4* vp = (const float4*)(ent + (size_t)c * 64) + q * 4;
                    const float4* ip = (const float4*)s_it4 + q * 4;
                    #pragma unroll
                    for (int i = 0; i < 4; ++i) {
                        float4 v = vp[i];
                        float4 w = ip[i];
                        dot += v.x*w.x + v.y*w.y + v.z*w.z + v.w*w.w;
                        ssq += v.x*v.x + v.y*v.y + v.z*v.z + v.w*v.w;
                    }
                }
                dot += __shfl_xor_sync(0xffffffffu, dot, 1);
                ssq += __shfl_xor_sync(0xffffffffu, ssq, 1);
                dot += __shfl_xor_sync(0xffffffffu, dot, 2);
                ssq += __shfl_xor_sync(0xffffffffu, ssq, 2);
                if (act && q == 0) {
                    float sim = dot / sqrtf(ssq);
                    if (s < ksel) s_simN[s] = sim;
                    else          s_simP[s - ksel] = sim;
                }
            }
        }
        __syncthreads();

        // ---- m and S over sampled negatives (warp 0) -----------------------
        if (warpId == 0 && ksel > 0) {
            float mm = -INFINITY;
            for (int s = lane; s < ksel; s += 32) mm = fmaxf(mm, s_simN[s]);
            #pragma unroll
            for (int o = 16; o; o >>= 1) mm = fmaxf(mm, __shfl_down_sync(0xffffffffu, mm, o));
            mm = __shfl_sync(0xffffffffu, mm, 0);
            float Ss = 0.0f;
            for (int s = lane; s < ksel; s += 32) Ss += expf(s_simN[s] - mm);
            #pragma unroll
            for (int o = 16; o; o >>= 1) Ss += __shfl_down_sync(0xffffffffu, Ss, o);
            if (lane == 0) { s_mS[0] = mm; s_mS[1] = Ss; }
        }
        __syncthreads();

        // ---- per-pair CE, row sum (warp 0) -> per-row globals --------------
        if (warpId == 0) {
            float acc = 0.0f;
            if (np > 0 && ksel > 0) {
                float m = s_mS[0], S = s_mS[1];
                for (int i = lane; i < np; i += 32) {
                    float sp = s_simP[i];
                    float pm = fmaxf(sp, m);
                    acc += logf(expf(sp - pm) + S * expf(m - pm)) + pm - sp;
                }
            }
            #pragma unroll
            for (int o = 16; o; o >>= 1) acc += __shfl_down_sync(0xffffffffu, acc, o);
            if (lane == 0) {
                g_rowLoss[row]  = (double)acc;
                g_rowPairs[row] = (np > 0 && ksel > 0) ? np : 0;
            }
        }
        __syncthreads();    // s_buf/s_n reused next row
    }

    // -------- last-CTA deterministic reduction ----------------------------
    if (tid == 0) {
        __threadfence();
        unsigned int t = atomicAdd(&g_done, 1u);
        s_last = (t == (unsigned int)(gridDim.x - 1));
    }
    __syncthreads();
    if (s_last) {
        double tsum = 0.0; long long psum = 0;
        for (int i = tid; i < I; i += 256) {
            tsum += g_rowLoss[i];
            psum += (long long)g_rowPairs[i];
        }
        s_red[tid] = tsum; s_redp[tid] = psum;
        __syncthreads();
        for (int o = 128; o; o >>= 1) {
            if (tid < o) {
                s_red[tid]  += s_red[tid + o];
                s_redp[tid] += s_redp[tid + o];
            }
            __syncthreads();
        }
        if (tid == 0) {
            out[0] = (s_redp[0] > 0) ? (float)(s_red[0] / (double)s_redp[0]) : 0.0f;
            g_done = 0;   // reset for next graph replay
        }
    }
}

extern "C" void kernel_launch(void* const* d_in, const int* in_sizes, int n_in,
                              void* d_out, int out_size) {
    const float* item = (const float*)d_in[0];
    const float* ent  = (const float*)d_in[1];
    const int*   adj  = (const int*)d_in[2];
    float* out = (float*)d_out;
    int I = in_sizes[0] / 64;          // 4096
    int E = in_sizes[1] / 64;          // 16384
    int grid = (I >= 1024) ? 1024 : I; // 4 rows/CTA, single resident wave
    infonce_row<<<grid, 256>>>(item, ent, adj, out, E, I);
}

// round 13
// speedup vs baseline: 1.0973x; 1.0973x over previous
#include <cuda_runtime.h>
#include <stdint.h>

// InfoNCE loss with exact JAX partitionable threefry2x32-20 sampling.
// bits[p] = x0 ^ x1 of threefry2x32(key=(0,42), counter=(0, p)), p = row*E+col.
// Single fused kernel, one CTA per row (best measured layout); last-CTA
// deterministic reduction. Streaming loop: branch-free predicated hit-push,
// 16 elements/iteration with two-deep int4 prefetch.

#define TEMP    0.07f
#define MAXB    384        // unified buffer: E[n]~161 (128 cand + 33 pos), >15 sigma
#define MAXP    128        // positives per row (expected ~33)
#define BITSCUT (1u << 25) // bits < 2^25  <=>  u < 1/128
#define NROWS   4096

static __device__ double g_rowLoss[NROWS];
static __device__ int    g_rowPairs[NROWS];
static __device__ unsigned int g_done = 0;

__device__ __forceinline__ uint32_t rotl32(uint32_t v, int r) {
    return __funnelshift_l(v, v, r);
}

// Threefry-2x32, 20 rounds, key=(0,42), counter=(0,p).
// xin must be p + 42 (= p + ks1, caller folds). Returns x0out ^ x1out.
__device__ __forceinline__ uint32_t threefry_bits(uint32_t xin) {
    const uint32_t ks1 = 42u;
    const uint32_t ks2 = 0x1BD11BDAu ^ 42u;
    uint32_t x1 = xin;
    uint32_t x0 = x1;                       // round 1 add from x0=0
    x1 = rotl32(x1, 13) ^ x0;
    x0 += x1;        x1 = rotl32(x1, 15) ^ x0;
    x0 += x1;        x1 = rotl32(x1, 26) ^ x0;
    x0 += x1;        x1 = rotl32(x1,  6) ^ x0;
    x1 += ks2 + 1u;                         // x1 injection, then x0 inj folds:
    x0 += x1 + ks1;  x1 = rotl32(x1, 17) ^ x0;
    x0 += x1;        x1 = rotl32(x1, 29) ^ x0;
    x0 += x1;        x1 = rotl32(x1, 16) ^ x0;
    x0 += x1;        x1 = rotl32(x1, 24) ^ x0;
    x1 += 2u;
    x0 += x1 + ks2;  x1 = rotl32(x1, 13) ^ x0;
    x0 += x1;        x1 = rotl32(x1, 15) ^ x0;
    x0 += x1;        x1 = rotl32(x1, 26) ^ x0;
    x0 += x1;        x1 = rotl32(x1,  6) ^ x0;
    x1 += ks1 + 3u;                         // x0 += ks0(=0): nothing
    x0 += x1;        x1 = rotl32(x1, 17) ^ x0;
    x0 += x1;        x1 = rotl32(x1, 29) ^ x0;
    x0 += x1;        x1 = rotl32(x1, 16) ^ x0;
    x0 += x1;        x1 = rotl32(x1, 24) ^ x0;
    x1 += ks2 + 4u;
    x0 += x1 + ks1;  x1 = rotl32(x1, 13) ^ x0;
    x0 += x1;        x1 = rotl32(x1, 15) ^ x0;
    x0 += x1;        x1 = rotl32(x1, 26) ^ x0;
    x0 += x1;        x1 = rotl32(x1,  6) ^ x0;
    return (x0 + ks2) ^ (x1 + 5u);
}

// Branch-free hit push (6 instrs): if (a>0 || bits<BITSCUT) append
// {col, a>0 ? 0xFFFFFFFF : bits}; shared counter carries the write ADDRESS.
__device__ __forceinline__ void push_hit(int a, uint32_t bits, uint32_t col,
                                         uint32_t ctr_addr, uint32_t buf_end) {
    asm volatile(
        "{\n\t"
        ".reg .pred p1, p, pb;\n\t"
        ".reg .u32 v, adr;\n\t"
        "setp.gt.s32 p1, %0, 0;\n\t"
        "setp.lt.or.u32 p, %1, %2, p1;\n\t"
        "selp.b32 v, 0xFFFFFFFF, %1, p1;\n\t"
        "@p atom.shared.add.u32 adr, [%3], 8;\n\t"
        "setp.lt.and.u32 pb, adr, %4, p;\n\t"
        "@pb st.shared.v2.u32 [adr], {%5, v};\n\t"
        "}"
        :: "r"(a), "r"(bits), "r"(BITSCUT), "r"(ctr_addr),
           "r"(buf_end), "r"(col)
        : "memory");
}

__global__ __launch_bounds__(256)
void infonce_row(const float* __restrict__ item,
                 const float* __restrict__ ent,
                 const int*   __restrict__ adj,
                 float* __restrict__ out,
                 int E, int I)
{
    __shared__ float4             s_it4[16];      // item row * 1/(||it||*T)
    __shared__ unsigned long long s_buf[MAXB];    // {col(lo32), key(hi32)}
    __shared__ unsigned short     s_pos[MAXP];    // positives, sorted by col
    __shared__ unsigned short     s_sel[MAXP];    // selected negs, by rank
    __shared__ float              s_simN[MAXP];
    __shared__ float              s_simP[MAXP];
    __shared__ unsigned int       s_n;            // write-address counter
    __shared__ int                s_last;
    __shared__ float              s_mS[2];
    __shared__ double             s_red[256];
    __shared__ long long          s_redp[256];

    float* s_it = (float*)s_it4;

    const int tid    = threadIdx.x;
    const int lane   = tid & 31;
    const int warpId = tid >> 5;
    const int row    = blockIdx.x;

    const uint32_t ctr_addr = (uint32_t)__cvta_generic_to_shared(&s_n);
    const uint32_t buf_addr = (uint32_t)__cvta_generic_to_shared(&s_buf[0]);
    const uint32_t buf_end  = buf_addr + MAXB * 8u;

    if (tid == 0) s_n = buf_addr;
    if (tid < 64) s_it[tid] = item[(size_t)row * 64 + tid];
    __syncthreads();
    if (tid < 32) {
        float a = s_it[lane], b = s_it[lane + 32];
        float ss = a * a + b * b;
        #pragma unroll
        for (int o = 16; o; o >>= 1) ss += __shfl_down_sync(0xffffffffu, ss, o);
        ss = __shfl_sync(0xffffffffu, ss, 0);
        float sc = 1.0f / (sqrtf(ss) * TEMP);
        s_it[lane]      = a * sc;
        s_it[lane + 32] = b * sc;
    }
    __syncthreads();

    const uint32_t base = (uint32_t)row * (uint32_t)E;
    const int* adjR = adj + (size_t)row * E;

    // ---- streaming pass: 16 elem/iter, branch-free, two-deep prefetch -----
    int c0 = tid * 16;
    int4 p0 = *(const int4*)(adjR + c0);
    int4 p1 = *(const int4*)(adjR + c0 + 4);
    int4 p2 = *(const int4*)(adjR + c0 + 8);
    int4 p3 = *(const int4*)(adjR + c0 + 12);
    #pragma unroll 1
    while (c0 < E) {
        const int4 c4a = p0, c4b = p1, c4c = p2, c4d = p3;
        const int cn = c0 + 4096;
        const int cs = (cn < E) ? cn : c0;            // safe prefetch address
        p0 = *(const int4*)(adjR + cs);
        p1 = *(const int4*)(adjR + cs + 4);
        p2 = *(const int4*)(adjR + cs + 8);
        p3 = *(const int4*)(adjR + cs + 12);

        const uint32_t pb42 = base + (uint32_t)c0 + 42u;   // p + ks1 base
        #pragma unroll
        for (int j = 0; j < 16; ++j) {
            uint32_t bits = threefry_bits(pb42 + (uint32_t)j);
            int a = (j< 4) ? ((j==0)?c4a.x:(j==1)?c4a.y:(j==2)?c4a.z:c4a.w)
                  : (j< 8) ? ((j==4)?c4b.x:(j==5)?c4b.y:(j==6)?c4b.z:c4b.w)
                  : (j<12) ? ((j==8)?c4c.x:(j==9)?c4c.y:(j==10)?c4c.z:c4c.w)
                           : ((j==12)?c4d.x:(j==13)?c4d.y:(j==14)?c4d.z:c4d.w);
            push_hit(a, bits, (uint32_t)c0 + (uint32_t)j, ctr_addr, buf_end);
        }
        c0 = cn;
    }
    __syncthreads();

    // ---- selection: one rank pass over unified buffer --------------------
    const int n = min((int)((s_n - buf_addr) >> 3), MAXB);
    bool isP = false; uint32_t hi = 0, col = 0;
    if (tid < n) {
        unsigned long long e = s_buf[tid];
        hi  = (uint32_t)(e >> 32);
        col = (uint32_t)e & 0xFFFFu;
        isP = (hi == 0xFFFFFFFFu);
    }
    const int npT   = __syncthreads_count(isP);   // total positives
    const int np    = min(npT, MAXP);
    const int k     = np;                 // k = min(num_pos, num_neg) = num_pos
    const int ncand = n - npT;
    const int ksel  = min(k, min(ncand, MAXP));

    // normalize: candidates -> (bits>>9)<<16 | col ; positives -> above all
    if (tid < n)
        s_buf[tid] = isP ? ((0x10000ULL << 16) | col)
                         : (((unsigned long long)(hi >> 9)) << 16) | col;
    __syncthreads();
    if (tid < n) {
        unsigned long long v = s_buf[tid];
        int rank = 0;
        for (int j = 0; j < n; ++j) rank += (s_buf[j] < v);
        if (isP) {
            int pr = rank - ncand;                 // positives rank above cands
            if (pr >= 0 && pr < MAXP) s_pos[pr] = (unsigned short)col;
        } else if (rank < ksel) {
            s_sel[rank] = (unsigned short)col;
        }
    }
    __syncthreads();

    // ---- cosine sims: 4 threads per entity row, 64 concurrent -------------
    {
        const int total = ksel + np;       // negatives first, then positives
        const int q = tid & 3;
        #pragma unroll 1
        for (int s0 = 0; s0 < total; s0 += 64) {
            const int s = s0 + (tid >> 2);
            const bool act = (s < total);
            float dot = 0.0f, ssq = 0.0f;
            if (act) {
                int c = (s < ksel) ? s_sel[s] : s_pos[s - ksel];
                const float4* vp = (const float4*)(ent + (size_t)c * 64) + q * 4;
                const float4* ip = (const float4*)s_it4 + q * 4;
                #pragma unroll
                for (int i = 0; i < 4; ++i) {
                    float4 v = vp[i];
                    float4 w = ip[i];
                    dot += v.x*w.x + v.y*w.y + v.z*w.z + v.w*w.w;
                    ssq += v.x*v.x + v.y*v.y + v.z*v.z + v.w*v.w;
                }
            }
            dot += __shfl_xor_sync(0xffffffffu, dot, 1);
            ssq += __shfl_xor_sync(0xffffffffu, ssq, 1);
            dot += __shfl_xor_sync(0xffffffffu, dot, 2);
            ssq += __shfl_xor_sync(0xffffffffu, ssq, 2);
            if (act && q == 0) {
                float sim = dot / sqrtf(ssq);
                if (s < ksel) s_simN[s] = sim;
                else          s_simP[s - ksel] = sim;
            }
        }
    }
    __syncthreads();

    // ---- m and S over sampled negatives (warp 0) --------------------------
    if (warpId == 0 && ksel > 0) {
        float mm = -INFINITY;
        for (int s = lane; s < ksel; s += 32) mm = fmaxf(mm, s_simN[s]);
        #pragma unroll
        for (int o = 16; o; o >>= 1) mm = fmaxf(mm, __shfl_down_sync(0xffffffffu, mm, o));
        mm = __shfl_sync(0xffffffffu, mm, 0);
        float Ss = 0.0f;
        for (int s = lane; s < ksel; s += 32) Ss += expf(s_simN[s] - mm);
        #pragma unroll
        for (int o = 16; o; o >>= 1) Ss += __shfl_down_sync(0xffffffffu, Ss, o);
        if (lane == 0) { s_mS[0] = mm; s_mS[1] = Ss; }
    }
    __syncthreads();

    // ---- per-pair CE, row sum (warp 0) -> per-row globals ------------------
    if (warpId == 0) {
        float acc = 0.0f;
        if (np > 0 && ksel > 0) {
            float m = s_mS[0], S = s_mS[1];
            for (int i = lane; i < np; i += 32) {
                float sp = s_simP[i];
                float pm = fmaxf(sp, m);
                acc += logf(expf(sp - pm) + S * expf(m - pm)) + pm - sp;
            }
        }
        #pragma unroll
        for (int o = 16; o; o >>= 1) acc += __shfl_down_sync(0xffffffffu, acc, o);
        if (lane == 0) {
            g_rowLoss[row]  = (double)acc;
            g_rowPairs[row] = (np > 0 && ksel > 0) ? np : 0;
        }
    }

    // ---- last-CTA deterministic reduction ----------------------------------
    if (tid == 0) {
        __threadfence();
        unsigned int t = atomicAdd(&g_done, 1u);
        s_last = (t == (unsigned int)(gridDim.x - 1));
    }
    __syncthreads();
    if (s_last) {
        double tsum = 0.0; long long psum = 0;
        for (int i = tid; i < I; i += 256) {
            tsum += g_rowLoss[i];
            psum += (long long)g_rowPairs[i];
        }
        s_red[tid] = tsum; s_redp[tid] = psum;
        __syncthreads();
        for (int o = 128; o; o >>= 1) {
            if (tid < o) {
                s_red[tid]  += s_red[tid + o];
                s_redp[tid] += s_redp[tid + o];
            }
            __syncthreads();
        }
        if (tid == 0) {
            out[0] = (s_redp[0] > 0) ? (float)(s_red[0] / (double)s_redp[0]) : 0.0f;
            g_done = 0;   // reset for next graph replay
        }
    }
}

extern "C" void kernel_launch(void* const* d_in, const int* in_sizes, int n_in,
                              void* d_out, int out_size) {
    const float* item = (const float*)d_in[0];
    const float* ent  = (const float*)d_in[1];
    const int*   adj  = (const int*)d_in[2];
    float* out = (float*)d_out;
    int I = in_sizes[0] / 64;
    int E = in_sizes[1] / 64;
    infonce_row<<<I, 256>>>(item, ent, adj, out, E, I);
}

// round 14
// speedup vs baseline: 1.0975x; 1.0001x over previous
#include <cuda_runtime.h>
#include <stdint.h>

// InfoNCE loss with exact JAX partitionable threefry2x32-20 sampling.
// bits[p] = x0 ^ x1 of threefry2x32(key=(0,42), counter=(0, p)), p = row*E+col.
// Single fused kernel, one CTA per row; last-CTA deterministic reduction.
//
// Perf: ALU-pipe near saturation (87%). Half the threefry rotates are moved to
// the FMA pipe: rotl(v,r) = lo|hi of v*2^r (mul.wide.u32 = IMAD.WIDE), and the
// rotate-xor collapses to ONE LOP3 ((lo|hi)^x0, immLut 0x56). 10/20 rounds use
// the wide form (alternating) to balance ALU vs FMA pressure.

#define TEMP    0.07f
#define MAXB    384        // unified buffer: E[n]~161 (128 cand + 33 pos), >15 sigma
#define MAXP    128        // positives per row (expected ~33)
#define BITSCUT (1u << 25) // bits < 2^25  <=>  u < 1/128
#define NROWS   4096

static __device__ double g_rowLoss[NROWS];
static __device__ int    g_rowPairs[NROWS];
static __device__ unsigned int g_done = 0;

// rotate-xor, ALU form: SHF + LOP3
__device__ __forceinline__ uint32_t rx_s(uint32_t x1, int r, uint32_t x0) {
    return __funnelshift_l(x1, x1, r) ^ x0;
}
// rotate-xor, FMA form: IMAD.WIDE (fma pipe) + single LOP3 ((lo|hi)^x0 = 0x56)
__device__ __forceinline__ uint32_t rx_w(uint32_t x1, uint32_t p2r, uint32_t x0) {
    uint64_t w;
    asm("mul.wide.u32 %0, %1, %2;" : "=l"(w) : "r"(x1), "r"(p2r));
    uint32_t lo = (uint32_t)w, hi = (uint32_t)(w >> 32), d;
    asm("lop3.b32 %0, %1, %2, %3, 0x56;" : "=r"(d) : "r"(lo), "r"(hi), "r"(x0));
    return d;
}

// Threefry-2x32, 20 rounds, key=(0,42), counter=(0,p).
// xin must be p + 42 (= p + ks1, caller folds). Returns x0out ^ x1out.
__device__ __forceinline__ uint32_t threefry_bits(uint32_t xin) {
    const uint32_t ks1 = 42u;
    const uint32_t ks2 = 0x1BD11BDAu ^ 42u;
    uint32_t x1 = xin;
    uint32_t x0 = x1;                        // round 1 add from x0=0
    x1 = rx_w(x1, 1u << 13, x0);
    x0 += x1;        x1 = rx_s(x1, 15, x0);
    x0 += x1;        x1 = rx_w(x1, 1u << 26, x0);
    x0 += x1;        x1 = rx_s(x1,  6, x0);
    x1 += ks2 + 1u;                          // x1 injection, x0 inj folds:
    x0 += x1 + ks1;  x1 = rx_w(x1, 1u << 17, x0);
    x0 += x1;        x1 = rx_s(x1, 29, x0);
    x0 += x1;        x1 = rx_w(x1, 1u << 16, x0);
    x0 += x1;        x1 = rx_s(x1, 24, x0);
    x1 += 2u;
    x0 += x1 + ks2;  x1 = rx_w(x1, 1u << 13, x0);
    x0 += x1;        x1 = rx_s(x1, 15, x0);
    x0 += x1;        x1 = rx_w(x1, 1u << 26, x0);
    x0 += x1;        x1 = rx_s(x1,  6, x0);
    x1 += ks1 + 3u;                          // x0 += ks0(=0): nothing
    x0 += x1;        x1 = rx_w(x1, 1u << 17, x0);
    x0 += x1;        x1 = rx_s(x1, 29, x0);
    x0 += x1;        x1 = rx_w(x1, 1u << 16, x0);
    x0 += x1;        x1 = rx_s(x1, 24, x0);
    x1 += ks2 + 4u;
    x0 += x1 + ks1;  x1 = rx_w(x1, 1u << 13, x0);
    x0 += x1;        x1 = rx_s(x1, 15, x0);
    x0 += x1;        x1 = rx_w(x1, 1u << 26, x0);
    x0 += x1;        x1 = rx_s(x1,  6, x0);
    return (x0 + ks2) ^ (x1 + 5u);
}

// Branch-free hit push (6 instrs): if (a>0 || bits<BITSCUT) append
// {col, a>0 ? 0xFFFFFFFF : bits}; shared counter carries the write ADDRESS.
__device__ __forceinline__ void push_hit(int a, uint32_t bits, uint32_t col,
                                         uint32_t ctr_addr, uint32_t buf_end) {
    asm volatile(
        "{\n\t"
        ".reg .pred p1, p, pb;\n\t"
        ".reg .u32 v, adr;\n\t"
        "setp.gt.s32 p1, %0, 0;\n\t"
        "setp.lt.or.u32 p, %1, %2, p1;\n\t"
        "selp.b32 v, 0xFFFFFFFF, %1, p1;\n\t"
        "@p atom.shared.add.u32 adr, [%3], 8;\n\t"
        "setp.lt.and.u32 pb, adr, %4, p;\n\t"
        "@pb st.shared.v2.u32 [adr], {%5, v};\n\t"
        "}"
        :: "r"(a), "r"(bits), "r"(BITSCUT), "r"(ctr_addr),
           "r"(buf_end), "r"(col)
        : "memory");
}

__global__ __launch_bounds__(256)
void infonce_row(const float* __restrict__ item,
                 const float* __restrict__ ent,
                 const int*   __restrict__ adj,
                 float* __restrict__ out,
                 int E, int I)
{
    __shared__ float4             s_it4[16];      // item row * 1/(||it||*T)
    __shared__ unsigned long long s_buf[MAXB];    // {col(lo32), key(hi32)}
    __shared__ unsigned short     s_pos[MAXP];    // positives, sorted by col
    __shared__ unsigned short     s_sel[MAXP];    // selected negs, by rank
    __shared__ float              s_simN[MAXP];
    __shared__ float              s_simP[MAXP];
    __shared__ unsigned int       s_n;            // write-address counter
    __shared__ int                s_last;
    __shared__ float              s_mS[2];
    __shared__ double             s_red[256];
    __shared__ long long          s_redp[256];

    float* s_it = (float*)s_it4;

    const int tid    = threadIdx.x;
    const int lane   = tid & 31;
    const int warpId = tid >> 5;
    const int row    = blockIdx.x;

    const uint32_t ctr_addr = (uint32_t)__cvta_generic_to_shared(&s_n);
    const uint32_t buf_addr = (uint32_t)__cvta_generic_to_shared(&s_buf[0]);
    const uint32_t buf_end  = buf_addr + MAXB * 8u;

    if (tid == 0) s_n = buf_addr;
    if (tid < 64) s_it[tid] = item[(size_t)row * 64 + tid];
    __syncthreads();
    if (tid < 32) {
        float a = s_it[lane], b = s_it[lane + 32];
        float ss = a * a + b * b;
        #pragma unroll
        for (int o = 16; o; o >>= 1) ss += __shfl_down_sync(0xffffffffu, ss, o);
        ss = __shfl_sync(0xffffffffu, ss, 0);
        float sc = 1.0f / (sqrtf(ss) * TEMP);
        s_it[lane]      = a * sc;
        s_it[lane + 32] = b * sc;
    }
    __syncthreads();

    const uint32_t base = (uint32_t)row * (uint32_t)E;
    const int* adjR = adj + (size_t)row * E;

    // ---- streaming pass: 16 elem/iter, branch-free, two-deep prefetch -----
    int c0 = tid * 16;
    int4 p0 = *(const int4*)(adjR + c0);
    int4 p1 = *(const int4*)(adjR + c0 + 4);
    int4 p2 = *(const int4*)(adjR + c0 + 8);
    int4 p3 = *(const int4*)(adjR + c0 + 12);
    #pragma unroll 1
    while (c0 < E) {
        const int4 c4a = p0, c4b = p1, c4c = p2, c4d = p3;
        const int cn = c0 + 4096;
        const int cs = (cn < E) ? cn : c0;            // safe prefetch address
        p0 = *(const int4*)(adjR + cs);
        p1 = *(const int4*)(adjR + cs + 4);
        p2 = *(const int4*)(adjR + cs + 8);
        p3 = *(const int4*)(adjR + cs + 12);

        const uint32_t pb42 = base + (uint32_t)c0 + 42u;   // p + ks1 base
        #pragma unroll
        for (int j = 0; j < 16; ++j) {
            uint32_t bits = threefry_bits(pb42 + (uint32_t)j);
            int a = (j< 4) ? ((j==0)?c4a.x:(j==1)?c4a.y:(j==2)?c4a.z:c4a.w)
                  : (j< 8) ? ((j==4)?c4b.x:(j==5)?c4b.y:(j==6)?c4b.z:c4b.w)
                  : (j<12) ? ((j==8)?c4c.x:(j==9)?c4c.y:(j==10)?c4c.z:c4c.w)
                           : ((j==12)?c4d.x:(j==13)?c4d.y:(j==14)?c4d.z:c4d.w);
            push_hit(a, bits, (uint32_t)c0 + (uint32_t)j, ctr_addr, buf_end);
        }
        c0 = cn;
    }
    __syncthreads();

    // ---- selection: one rank pass over unified buffer --------------------
    const int n = min((int)((s_n - buf_addr) >> 3), MAXB);
    bool isP = false; uint32_t hi = 0, col = 0;
    if (tid < n) {
        unsigned long long e = s_buf[tid];
        hi  = (uint32_t)(e >> 32);
        col = (uint32_t)e & 0xFFFFu;
        isP = (hi == 0xFFFFFFFFu);
    }
    const int npT   = __syncthreads_count(isP);   // total positives
    const int np    = min(npT, MAXP);
    const int k     = np;                 // k = min(num_pos, num_neg) = num_pos
    const int ncand = n - npT;
    const int ksel  = min(k, min(ncand, MAXP));

    // normalize: candidates -> (bits>>9)<<16 | col ; positives -> above all
    if (tid < n)
        s_buf[tid] = isP ? ((0x10000ULL << 16) | col)
                         : (((unsigned long long)(hi >> 9)) << 16) | col;
    __syncthreads();
    if (tid < n) {
        unsigned long long v = s_buf[tid];
        int rank = 0;
        for (int j = 0; j < n; ++j) rank += (s_buf[j] < v);
        if (isP) {
            int pr = rank - ncand;                 // positives rank above cands
            if (pr >= 0 && pr < MAXP) s_pos[pr] = (unsigned short)col;
        } else if (rank < ksel) {
            s_sel[rank] = (unsigned short)col;
        }
    }
    __syncthreads();

    // ---- cosine sims: 4 threads per entity row, 64 concurrent -------------
    {
        const int total = ksel + np;       // negatives first, then positives
        const int q = tid & 3;
        #pragma unroll 1
        for (int s0 = 0; s0 < total; s0 += 64) {
            const int s = s0 + (tid >> 2);
            const bool act = (s < total);
            float dot = 0.0f, ssq = 0.0f;
            if (act) {
                int c = (s < ksel) ? s_sel[s] : s_pos[s - ksel];
                const float4* vp = (const float4*)(ent + (size_t)c * 64) + q * 4;
                const float4* ip = (const float4*)s_it4 + q * 4;
                #pragma unroll
                for (int i = 0; i < 4; ++i) {
                    float4 v = vp[i];
                    float4 w = ip[i];
                    dot += v.x*w.x + v.y*w.y + v.z*w.z + v.w*w.w;
                    ssq += v.x*v.x + v.y*v.y + v.z*v.z + v.w*v.w;
                }
            }
            dot += __shfl_xor_sync(0xffffffffu, dot, 1);
            ssq += __shfl_xor_sync(0xffffffffu, ssq, 1);
            dot += __shfl_xor_sync(0xffffffffu, dot, 2);
            ssq += __shfl_xor_sync(0xffffffffu, ssq, 2);
            if (act && q == 0) {
                float sim = dot / sqrtf(ssq);
                if (s < ksel) s_simN[s] = sim;
                else          s_simP[s - ksel] = sim;
            }
        }
    }
    __syncthreads();

    // ---- m and S over sampled negatives (warp 0) --------------------------
    if (warpId == 0 && ksel > 0) {
        float mm = -INFINITY;
        for (int s = lane; s < ksel; s += 32) mm = fmaxf(mm, s_simN[s]);
        #pragma unroll
        for (int o = 16; o; o >>= 1) mm = fmaxf(mm, __shfl_down_sync(0xffffffffu, mm, o));
        mm = __shfl_sync(0xffffffffu, mm, 0);
        float Ss = 0.0f;
        for (int s = lane; s < ksel; s += 32) Ss += expf(s_simN[s] - mm);
        #pragma unroll
        for (int o = 16; o; o >>= 1) Ss += __shfl_down_sync(0xffffffffu, Ss, o);
        if (lane == 0) { s_mS[0] = mm; s_mS[1] = Ss; }
    }
    __syncthreads();

    // ---- per-pair CE, row sum (warp 0) -> per-row globals ------------------
    if (warpId == 0) {
        float acc = 0.0f;
        if (np > 0 && ksel > 0) {
            float m = s_mS[0], S = s_mS[1];
            for (int i = lane; i < np; i += 32) {
                float sp = s_simP[i];
                float pm = fmaxf(sp, m);
                acc += logf(expf(sp - pm) + S * expf(m - pm)) + pm - sp;
            }
        }
        #pragma unroll
        for (int o = 16; o; o >>= 1) acc += __shfl_down_sync(0xffffffffu, acc, o);
        if (lane == 0) {
            g_rowLoss[row]  = (double)acc;
            g_rowPairs[row] = (np > 0 && ksel > 0) ? np : 0;
        }
    }

    // ---- last-CTA deterministic reduction ----------------------------------
    if (tid == 0) {
        __threadfence();
        unsigned int t = atomicAdd(&g_done, 1u);
        s_last = (t == (unsigned int)(gridDim.x - 1));
    }
    __syncthreads();
    if (s_last) {
        double tsum = 0.0; long long psum = 0;
        for (int i = tid; i < I; i += 256) {
            tsum += g_rowLoss[i];
            psum += (long long)g_rowPairs[i];
        }
        s_red[tid] = tsum; s_redp[tid] = psum;
        __syncthreads();
        for (int o = 128; o; o >>= 1) {
            if (tid < o) {
                s_red[tid]  += s_red[tid + o];
                s_redp[tid] += s_redp[tid + o];
            }
            __syncthreads();
        }
        if (tid == 0) {
            out[0] = (s_redp[0] > 0) ? (float)(s_red[0] / (double)s_redp[0]) : 0.0f;
            g_done = 0;   // reset for next graph replay
        }
    }
}

extern "C" void kernel_launch(void* const* d_in, const int* in_sizes, int n_in,
                              void* d_out, int out_size) {
    const float* item = (const float*)d_in[0];
    const float* ent  = (const float*)d_in[1];
    const int*   adj  = (const int*)d_in[2];
    float* out = (float*)d_out;
    int I = in_sizes[0] / 64;
    int E = in_sizes[1] / 64;
    infonce_row<<<I, 256>>>(item, ent, adj, out, E, I);
}